// round 4
// baseline (speedup 1.0000x reference)
#include <cuda_runtime.h>
#include <cuda_bf16.h>
#include <cstdint>

#define B_    8
#define S_    2048
#define E_    768
#define FF_   3072
#define NQ_   128
#define NTOK  (B_ * S_)

// ---------------- static scratch (device globals; allocation-free) ----------------
__device__ float g_qa [NTOK * E_];                 //  50 MB  cos(proj+theta_rx), [tok][e]
__device__ float g_sc [B_ * S_ * S_];              // 134 MB  scores / probs, [b][s][t]
__device__ float g_att[NTOK * E_];                 //  50 MB  attn output
__device__ float g_x1 [NTOK * E_];                 //  50 MB  LN1 output
__device__ float g_qf [NTOK * NQ_];                //   8 MB  cos(x1[:,:NQ]+theta_ry)
__device__ float g_h  [NTOK * FF_];                // 201 MB  relu hidden
__device__ float g_ffn[NTOK * E_];                 //  50 MB  ffn output

// ---------------- small PTX helpers ----------------
__device__ __forceinline__ uint32_t f2tf(float f) {
    uint32_t u;
    asm("cvt.rna.tf32.f32 %0, %1;" : "=r"(u) : "f"(f));
    return u;
}

__device__ __forceinline__ void mma_tf32(float c[4], const uint32_t a[4], const uint32_t b[2]) {
    asm volatile(
        "mma.sync.aligned.m16n8k8.row.col.f32.tf32.tf32.f32 "
        "{%0,%1,%2,%3}, {%4,%5,%6,%7}, {%8,%9}, {%0,%1,%2,%3};\n"
        : "+f"(c[0]), "+f"(c[1]), "+f"(c[2]), "+f"(c[3])
        : "r"(a[0]), "r"(a[1]), "r"(a[2]), "r"(a[3]), "r"(b[0]), "r"(b[1]));
}

__device__ __forceinline__ void cp16(float* dst, const float* src) {
    unsigned d = (unsigned)__cvta_generic_to_shared(dst);
    asm volatile("cp.async.cg.shared.global [%0], [%1], 16;" :: "r"(d), "l"(src));
}

// ---------------- generic TF32 GEMM ----------------
//   BTRANS=true : C[M,N] = A[M,K] @ B[N,K]^T   (B row n is K-contiguous)
//   BTRANS=false: C[M,N] = A[M,K] @ B[K,N]     (B row k is N-contiguous)
// Block tile 128x128, BK=16, 128 threads = 4 warps (2x2), warp tile 64x64.
enum { EPI_QA = 0, EPI_SCORES = 1, EPI_NONE = 2, EPI_RELU = 3, EPI_BIAS = 4 };

template <int EPI, bool BTRANS>
__global__ __launch_bounds__(128)
void gemm_tf32(const float* __restrict__ Aall, const float* __restrict__ Ball,
               float* __restrict__ Call,
               int K, int lda, int ldb, int ldc,
               long bsA, long bsB, long bsC,
               const float* __restrict__ vec)
{
    constexpr int BM = 128, BN = 128, BK = 16;
    constexpr int LDA = BK + 4;          // 20 : sA[row][k]
    constexpr int LDBNN = BN + 4;        // 132: sBkn[k][n]
    __shared__ float sA[2][BM][LDA];
    __shared__ float sB[2][BTRANS ? (BN * LDA) : (BK * LDBNN)];

    const float* A  = Aall + (long)blockIdx.z * bsA;
    const float* Bp = Ball + (long)blockIdx.z * bsB;
    float*       C  = Call + (long)blockIdx.z * bsC;

    const int tid  = threadIdx.x;
    const int wid  = tid >> 5, lane = tid & 31;
    const int wm   = wid & 1,  wn   = wid >> 1;      // 2 x 2 warps, each 64x64
    const int r    = lane >> 2, cq  = lane & 3;

    const int row0 = blockIdx.y * BM;
    const int col0 = blockIdx.x * BN;

    float acc[4][8][4];
#pragma unroll
    for (int i = 0; i < 4; i++)
#pragma unroll
        for (int j = 0; j < 8; j++)
#pragma unroll
            for (int k = 0; k < 4; k++) acc[i][j][k] = 0.f;

    const int nk = K / BK;

    auto load_stage = [&](int buf, int kt) {
        const int kbase = kt * BK;
#pragma unroll
        for (int u = 0; u < 4; u++) {                 // 512 16B chunks / 128 thr
            int c  = tid + u * 128;
            int rw = c >> 2, kq = c & 3;
            cp16(&sA[buf][rw][kq * 4], A + (long)(row0 + rw) * lda + kbase + kq * 4);
        }
        if (BTRANS) {
#pragma unroll
            for (int u = 0; u < 4; u++) {
                int c  = tid + u * 128;
                int rw = c >> 2, kq = c & 3;
                cp16(&sB[buf][rw * LDA + kq * 4],
                     Bp + (long)(col0 + rw) * ldb + kbase + kq * 4);
            }
        } else {
#pragma unroll
            for (int u = 0; u < 4; u++) {             // 16 k-rows x 32 chunks
                int c  = tid + u * 128;
                int kk = c >> 5, nq = c & 31;
                cp16(&sB[buf][kk * LDBNN + nq * 4],
                     Bp + (long)(kbase + kk) * ldb + col0 + nq * 4);
            }
        }
        asm volatile("cp.async.commit_group;");
    };

    load_stage(0, 0);

    for (int kt = 0; kt < nk; kt++) {
        if (kt + 1 < nk) {
            load_stage((kt + 1) & 1, kt + 1);
            asm volatile("cp.async.wait_group 1;");
        } else {
            asm volatile("cp.async.wait_group 0;");
        }
        __syncthreads();
        const int buf = kt & 1;
#pragma unroll
        for (int ks = 0; ks < BK; ks += 8) {
            uint32_t af[4][4], bf[8][2];
#pragma unroll
            for (int i = 0; i < 4; i++) {
                int m = wm * 64 + i * 16;
                af[i][0] = f2tf(sA[buf][m + r    ][ks + cq    ]);
                af[i][1] = f2tf(sA[buf][m + r + 8][ks + cq    ]);
                af[i][2] = f2tf(sA[buf][m + r    ][ks + cq + 4]);
                af[i][3] = f2tf(sA[buf][m + r + 8][ks + cq + 4]);
            }
#pragma unroll
            for (int j = 0; j < 8; j++) {
                int n = wn * 64 + j * 8 + r;
                if (BTRANS) {
                    bf[j][0] = f2tf(sB[buf][n * LDA + ks + cq    ]);
                    bf[j][1] = f2tf(sB[buf][n * LDA + ks + cq + 4]);
                } else {
                    bf[j][0] = f2tf(sB[buf][(ks + cq    ) * LDBNN + n]);
                    bf[j][1] = f2tf(sB[buf][(ks + cq + 4) * LDBNN + n]);
                }
            }
#pragma unroll
            for (int i = 0; i < 4; i++)
#pragma unroll
                for (int j = 0; j < 8; j++)
                    mma_tf32(acc[i][j], af[i], bf[j]);
        }
        __syncthreads();
    }

    // ---------------- epilogue ----------------
    const float scale = 0.35355339059327376f;  // 1/sqrt(8)
#pragma unroll
    for (int i = 0; i < 4; i++) {
        int gm = row0 + wm * 64 + i * 16 + r;
#pragma unroll
        for (int j = 0; j < 8; j++) {
            int gn = col0 + wn * 64 + j * 8 + 2 * cq;
#pragma unroll
            for (int hh = 0; hh < 2; hh++) {
                int gmr = gm + hh * 8;
                float e0 = acc[i][j][hh * 2 + 0];
                float e1 = acc[i][j][hh * 2 + 1];
                if (EPI == EPI_QA) {
                    e0 = cosf(e0 + vec[gn]);
                    e1 = cosf(e1 + vec[gn + 1]);
                } else if (EPI == EPI_SCORES) {
                    e0 *= scale; e1 *= scale;
                } else if (EPI == EPI_RELU) {
                    e0 = fmaxf(e0 + vec[gn], 0.f);
                    e1 = fmaxf(e1 + vec[gn + 1], 0.f);
                } else if (EPI == EPI_BIAS) {
                    e0 += vec[gn];
                    e1 += vec[gn + 1];
                }
                *reinterpret_cast<float2*>(&C[(long)gmr * ldc + gn]) = make_float2(e0, e1);
            }
        }
    }
}

// ---------------- block reductions ----------------
__device__ __forceinline__ float blk_sum(float v, float* sh) {
#pragma unroll
    for (int o = 16; o > 0; o >>= 1) v += __shfl_xor_sync(0xffffffffu, v, o);
    int w = threadIdx.x >> 5;
    if ((threadIdx.x & 31) == 0) sh[w] = v;
    __syncthreads();
    float t = 0.f;
#pragma unroll
    for (int i = 0; i < 8; i++) t += sh[i];
    __syncthreads();
    return t;
}

__device__ __forceinline__ float blk_max(float v, float* sh) {
#pragma unroll
    for (int o = 16; o > 0; o >>= 1) v = fmaxf(v, __shfl_xor_sync(0xffffffffu, v, o));
    int w = threadIdx.x >> 5;
    if ((threadIdx.x & 31) == 0) sh[w] = v;
    __syncthreads();
    float t = sh[0];
#pragma unroll
    for (int i = 1; i < 8; i++) t = fmaxf(t, sh[i]);
    __syncthreads();
    return t;
}

// ---------------- softmax over each score row (S_=2048 cols) ----------------
__global__ __launch_bounds__(256)
void softmax_kernel()
{
    __shared__ float sh[8];
    const long row = blockIdx.x;                   // 0..NTOK-1; g_sc is [NTOK][S_]
    float* sr = g_sc + row * (long)S_;
    const int tid = threadIdx.x;

    float v[8];
    float m = -1e30f;
#pragma unroll
    for (int k = 0; k < 8; k++) { v[k] = sr[tid + k * 256]; m = fmaxf(m, v[k]); }
    m = blk_max(m, sh);

    float s = 0.f;
#pragma unroll
    for (int k = 0; k < 8; k++) { v[k] = __expf(v[k] - m); s += v[k]; }
    s = blk_sum(s, sh);

    const float inv = 1.f / s;
#pragma unroll
    for (int k = 0; k < 8; k++) sr[tid + k * 256] = v[k] * inv;
}

// ---------------- LN1 (x + att) -> x1, and qf = cos(x1[:, :NQ] + theta_ry) ----------------
__global__ __launch_bounds__(256)
void ln1_qf_kernel(const float* __restrict__ x, const float* __restrict__ g,
                   const float* __restrict__ be, const float* __restrict__ th_ry)
{
    __shared__ float sh[8];
    const long row = blockIdx.x;
    const int tid = threadIdx.x;
    const float* xr = x     + row * (long)E_;
    const float* ar = g_att + row * (long)E_;

    float v[3]; float s = 0.f;
#pragma unroll
    for (int k = 0; k < 3; k++) { int j = tid + 256 * k; v[k] = xr[j] + ar[j]; s += v[k]; }
    float mean = blk_sum(s, sh) * (1.0f / 768.0f);

    float q = 0.f;
#pragma unroll
    for (int k = 0; k < 3; k++) { float d = v[k] - mean; q += d * d; }
    float rstd = rsqrtf(blk_sum(q, sh) * (1.0f / 768.0f) + 1e-5f);

#pragma unroll
    for (int k = 0; k < 3; k++) {
        int j = tid + 256 * k;
        float y = (v[k] - mean) * rstd * g[j] + be[j];
        g_x1[row * (long)E_ + j] = y;
        if (j < NQ_) g_qf[row * (long)NQ_ + j] = cosf(y + th_ry[j]);
    }
}

// ---------------- LN2 (x1 + ffn) -> out ----------------
__global__ __launch_bounds__(256)
void ln2_kernel(const float* __restrict__ g, const float* __restrict__ be,
                float* __restrict__ out)
{
    __shared__ float sh[8];
    const long row = blockIdx.x;
    const int tid = threadIdx.x;
    const float* xr = g_x1  + row * (long)E_;
    const float* fr = g_ffn + row * (long)E_;

    float v[3]; float s = 0.f;
#pragma unroll
    for (int k = 0; k < 3; k++) { int j = tid + 256 * k; v[k] = xr[j] + fr[j]; s += v[k]; }
    float mean = blk_sum(s, sh) * (1.0f / 768.0f);

    float q = 0.f;
#pragma unroll
    for (int k = 0; k < 3; k++) { float d = v[k] - mean; q += d * d; }
    float rstd = rsqrtf(blk_sum(q, sh) * (1.0f / 768.0f) + 1e-5f);

#pragma unroll
    for (int k = 0; k < 3; k++) {
        int j = tid + 256 * k;
        out[row * (long)E_ + j] = (v[k] - mean) * rstd * g[j] + be[j];
    }
}

// ---------------- launch ----------------
extern "C" void kernel_launch(void* const* d_in, const int* in_sizes, int n_in,
                              void* d_out, int out_size)
{
    (void)in_sizes; (void)n_in; (void)out_size;
    const float* x     = (const float*)d_in[0];
    const float* Wp    = (const float*)d_in[1];
    const float* th_rx = (const float*)d_in[2];
    const float* th_ry = (const float*)d_in[3];
    const float* W1    = (const float*)d_in[4];
    const float* b1    = (const float*)d_in[5];
    const float* W2    = (const float*)d_in[6];
    const float* b2    = (const float*)d_in[7];
    const float* g1    = (const float*)d_in[8];
    const float* be1   = (const float*)d_in[9];
    const float* g2    = (const float*)d_in[10];
    const float* be2   = (const float*)d_in[11];
    float* out = (float*)d_out;

    void *p;
    cudaGetSymbolAddress(&p, g_qa);  float* qa  = (float*)p;
    cudaGetSymbolAddress(&p, g_sc);  float* sc  = (float*)p;
    cudaGetSymbolAddress(&p, g_att); float* att = (float*)p;
    cudaGetSymbolAddress(&p, g_qf);  float* qf  = (float*)p;
    cudaGetSymbolAddress(&p, g_h);   float* h   = (float*)p;
    cudaGetSymbolAddress(&p, g_ffn); float* ffn = (float*)p;

    dim3 blk(128);

    // 1) proj + cos -> qa
    gemm_tf32<EPI_QA, true><<<dim3(E_ / 128, NTOK / 128, 1), blk>>>(
        x, Wp, qa, E_, E_, E_, E_, 0, 0, 0, th_rx);

    // 2) scores = qa qa^T / sqrt(8), batched over 8
    gemm_tf32<EPI_SCORES, true><<<dim3(S_ / 128, S_ / 128, B_), blk>>>(
        qa, qa, sc, E_, E_, E_, S_,
        (long)S_ * E_, (long)S_ * E_, (long)S_ * S_, nullptr);

    // 3) softmax rows
    softmax_kernel<<<NTOK, 256>>>();

    // 4) attn_out = P @ qa  (NN: B = qa[t][e])
    gemm_tf32<EPI_NONE, false><<<dim3(E_ / 128, S_ / 128, B_), blk>>>(
        sc, qa, att, S_, S_, E_, E_,
        (long)S_ * S_, (long)S_ * E_, (long)S_ * E_, nullptr);

    // 5) x1 = LN(x + att); qf = cos(x1[:, :NQ] + theta_ry)
    ln1_qf_kernel<<<NTOK, 256>>>(x, g1, be1, th_ry);

    // 6) h = relu(qf @ W1^T + b1)
    gemm_tf32<EPI_RELU, true><<<dim3(FF_ / 128, NTOK / 128, 1), blk>>>(
        qf, W1, h, NQ_, NQ_, NQ_, FF_, 0, 0, 0, b1);

    // 7) ffn = h @ W2^T + b2
    gemm_tf32<EPI_BIAS, true><<<dim3(E_ / 128, NTOK / 128, 1), blk>>>(
        h, W2, ffn, FF_, FF_, FF_, E_, 0, 0, 0, b2);

    // 8) out = LN(x1 + ffn)
    ln2_kernel<<<NTOK, 256>>>(g2, be2, out);
}

// round 9
// speedup vs baseline: 1.0112x; 1.0112x over previous
#include <cuda_runtime.h>
#include <cuda_bf16.h>
#include <cstdint>

#define B_    8
#define S_    2048
#define E_    768
#define FF_   3072
#define NQ_   128
#define NTOK  (B_ * S_)

// ---------------- static scratch (device globals; allocation-free) ----------------
__device__ float g_xr [NTOK * E_];                 //  50 MB  tf32-rounded x
__device__ float g_wpr[E_ * E_];                   // 2.4 MB  tf32-rounded Wp
__device__ float g_w1r[FF_ * NQ_];                 // 1.5 MB  tf32-rounded W1
__device__ float g_w2r[E_ * FF_];                  // 9.4 MB  tf32-rounded W2
__device__ float g_qa [NTOK * E_];                 //  50 MB  cos(proj+theta_rx), rounded
__device__ float g_qaT[B_ * E_ * S_];              //  50 MB  [b][e][s], rounded
__device__ float g_sc [(long)B_ * S_ * S_];        // 134 MB  scores / probs (rounded)
__device__ float g_att[NTOK * E_];                 //  50 MB
__device__ float g_x1 [NTOK * E_];                 //  50 MB
__device__ float g_qf [NTOK * NQ_];                //   8 MB  rounded
__device__ float g_h  [NTOK * FF_];                // 201 MB  rounded
__device__ float g_ffn[NTOK * E_];                 //  50 MB

// ---------------- helpers ----------------
__device__ __forceinline__ uint32_t f2tf(float f) {
    uint32_t u;
    asm("cvt.rna.tf32.f32 %0, %1;" : "=r"(u) : "f"(f));
    return u;
}
__device__ __forceinline__ float round_tf(float f) { return __uint_as_float(f2tf(f)); }

__device__ __forceinline__ void mma_tf32(float c[4], const uint32_t a[4], const uint32_t b[2]) {
    asm volatile(
        "mma.sync.aligned.m16n8k8.row.col.f32.tf32.tf32.f32 "
        "{%0,%1,%2,%3}, {%4,%5,%6,%7}, {%8,%9}, {%0,%1,%2,%3};\n"
        : "+f"(c[0]), "+f"(c[1]), "+f"(c[2]), "+f"(c[3])
        : "r"(a[0]), "r"(a[1]), "r"(a[2]), "r"(a[3]), "r"(b[0]), "r"(b[1]));
}

__device__ __forceinline__ void cp16(void* dst, const float* src) {
    unsigned d = (unsigned)__cvta_generic_to_shared(dst);
    asm volatile("cp.async.cg.shared.global [%0], [%1], 16;" :: "r"(d), "l"(src));
}

// ---------------- tf32 GEMM, TN: C[M,N] = A[M,K] @ B[N,K]^T ----------------
// EXACT R1 structure: BM=BN=128, BK=16, 256 threads = 8 warps (2m x 4n),
// warp tile 64x32, padded smem (LDS=20). Operands pre-rounded to tf32 ->
// fragments loaded directly as uint32 (no cvt in mainloop).
enum { EPI_QA = 0, EPI_SCORES = 1, EPI_NONE = 2, EPI_RELU = 3, EPI_BIAS = 4 };

template <int EPI>
__global__ __launch_bounds__(256)
void gemm_tf32(const float* __restrict__ Aall, const float* __restrict__ Ball,
               float* __restrict__ Call,
               int K, int lda, int ldb, int ldc,
               long bsA, long bsB, long bsC,
               const float* __restrict__ vec)
{
    constexpr int BM = 128, BN = 128, BK = 16, LDS = BK + 4;
    __shared__ uint32_t sA[2][BM][LDS];
    __shared__ uint32_t sB[2][BN][LDS];

    const float* A  = Aall + (long)blockIdx.z * bsA;
    const float* Bp = Ball + (long)blockIdx.z * bsB;
    float*       C  = Call + (long)blockIdx.z * bsC;

    const int tid  = threadIdx.x;
    const int wid  = tid >> 5, lane = tid & 31;
    const int wm   = wid & 1,  wn   = wid >> 1;      // 2 x 4 warps
    const int r    = lane >> 2, cq  = lane & 3;

    const int row0 = blockIdx.y * BM;
    const int col0 = blockIdx.x * BN;

    float acc[4][4][4];
#pragma unroll
    for (int i = 0; i < 4; i++)
#pragma unroll
        for (int j = 0; j < 4; j++)
#pragma unroll
            for (int k = 0; k < 4; k++) acc[i][j][k] = 0.f;

    const int nk = K / BK;

    auto load_stage = [&](int buf, int kt) {
        const int kbase = kt * BK;
#pragma unroll
        for (int u = 0; u < 2; u++) {          // 512 16B chunks per operand
            int c  = tid + u * 256;
            int rw = c >> 2, kq = c & 3;
            cp16(&sA[buf][rw][kq * 4], A  + (long)(row0 + rw) * lda + kbase + kq * 4);
            cp16(&sB[buf][rw][kq * 4], Bp + (long)(col0 + rw) * ldb + kbase + kq * 4);
        }
        asm volatile("cp.async.commit_group;");
    };

    load_stage(0, 0);

    for (int kt = 0; kt < nk; kt++) {
        if (kt + 1 < nk) {
            load_stage((kt + 1) & 1, kt + 1);
            asm volatile("cp.async.wait_group 1;");
        } else {
            asm volatile("cp.async.wait_group 0;");
        }
        __syncthreads();
        const int buf = kt & 1;
#pragma unroll
        for (int ks = 0; ks < BK; ks += 8) {
            uint32_t af[4][4], bf[4][2];
#pragma unroll
            for (int i = 0; i < 4; i++) {
                int m = wm * 64 + i * 16;
                af[i][0] = sA[buf][m + r    ][ks + cq    ];
                af[i][1] = sA[buf][m + r + 8][ks + cq    ];
                af[i][2] = sA[buf][m + r    ][ks + cq + 4];
                af[i][3] = sA[buf][m + r + 8][ks + cq + 4];
            }
#pragma unroll
            for (int j = 0; j < 4; j++) {
                int n = wn * 32 + j * 8;
                bf[j][0] = sB[buf][n + r][ks + cq    ];
                bf[j][1] = sB[buf][n + r][ks + cq + 4];
            }
#pragma unroll
            for (int i = 0; i < 4; i++)
#pragma unroll
                for (int j = 0; j < 4; j++)
                    mma_tf32(acc[i][j], af[i], bf[j]);
        }
        __syncthreads();
    }

    // ---------------- epilogue (R1-proven layout) ----------------
    const float scale = 0.35355339059327376f;  // 1/sqrt(8)
#pragma unroll
    for (int i = 0; i < 4; i++) {
        int gm = row0 + wm * 64 + i * 16 + r;
#pragma unroll
        for (int j = 0; j < 4; j++) {
            int gn = col0 + wn * 32 + j * 8 + 2 * cq;
#pragma unroll
            for (int hh = 0; hh < 2; hh++) {
                int gmr = gm + hh * 8;
                float e0 = acc[i][j][hh * 2 + 0];
                float e1 = acc[i][j][hh * 2 + 1];
                if (EPI == EPI_QA) {
                    float q0 = round_tf(cosf(e0 + vec[gn]));
                    float q1 = round_tf(cosf(e1 + vec[gn + 1]));
                    *reinterpret_cast<float2*>(&C[(long)gmr * ldc + gn]) = make_float2(q0, q1);
                    int bb = gmr >> 11, ss = gmr & (S_ - 1);
                    g_qaT[((long)bb * E_ + gn    ) * S_ + ss] = q0;
                    g_qaT[((long)bb * E_ + gn + 1) * S_ + ss] = q1;
                } else {
                    if (EPI == EPI_SCORES) { e0 *= scale; e1 *= scale; }
                    else if (EPI == EPI_RELU) {
                        e0 = round_tf(fmaxf(e0 + vec[gn], 0.f));
                        e1 = round_tf(fmaxf(e1 + vec[gn + 1], 0.f));
                    } else if (EPI == EPI_BIAS) {
                        e0 += vec[gn];
                        e1 += vec[gn + 1];
                    }
                    *reinterpret_cast<float2*>(&C[(long)gmr * ldc + gn]) = make_float2(e0, e1);
                }
            }
        }
    }
}

// ---------------- elementwise tf32 rounding ----------------
__global__ __launch_bounds__(256)
void round_kernel(const float* __restrict__ in, float* __restrict__ out, long n4)
{
    long i = (long)blockIdx.x * 256 + threadIdx.x;
    if (i < n4) {
        float4 v = reinterpret_cast<const float4*>(in)[i];
        v.x = round_tf(v.x); v.y = round_tf(v.y);
        v.z = round_tf(v.z); v.w = round_tf(v.w);
        reinterpret_cast<float4*>(out)[i] = v;
    }
}

// ---------------- block reductions ----------------
__device__ __forceinline__ float blk_sum(float v, float* sh) {
#pragma unroll
    for (int o = 16; o > 0; o >>= 1) v += __shfl_xor_sync(0xffffffffu, v, o);
    int w = threadIdx.x >> 5;
    if ((threadIdx.x & 31) == 0) sh[w] = v;
    __syncthreads();
    float t = 0.f;
#pragma unroll
    for (int i = 0; i < 8; i++) t += sh[i];
    __syncthreads();
    return t;
}
__device__ __forceinline__ float blk_max(float v, float* sh) {
#pragma unroll
    for (int o = 16; o > 0; o >>= 1) v = fmaxf(v, __shfl_xor_sync(0xffffffffu, v, o));
    int w = threadIdx.x >> 5;
    if ((threadIdx.x & 31) == 0) sh[w] = v;
    __syncthreads();
    float t = sh[0];
#pragma unroll
    for (int i = 1; i < 8; i++) t = fmaxf(t, sh[i]);
    __syncthreads();
    return t;
}

// ---------------- softmax rows (probs rounded to tf32) ----------------
__global__ __launch_bounds__(256)
void softmax_kernel()
{
    __shared__ float sh[8];
    const long row = blockIdx.x;
    float* sr = g_sc + row * (long)S_;
    const int tid = threadIdx.x;

    float v[8];
    float m = -1e30f;
#pragma unroll
    for (int k = 0; k < 8; k++) { v[k] = sr[tid + k * 256]; m = fmaxf(m, v[k]); }
    m = blk_max(m, sh);

    float s = 0.f;
#pragma unroll
    for (int k = 0; k < 8; k++) { v[k] = __expf(v[k] - m); s += v[k]; }
    s = blk_sum(s, sh);

    const float inv = 1.f / s;
#pragma unroll
    for (int k = 0; k < 8; k++) sr[tid + k * 256] = round_tf(v[k] * inv);
}

// ---------------- LN1 -> x1, qf (rounded) ----------------
__global__ __launch_bounds__(256)
void ln1_qf_kernel(const float* __restrict__ x, const float* __restrict__ g,
                   const float* __restrict__ be, const float* __restrict__ th_ry)
{
    __shared__ float sh[8];
    const long row = blockIdx.x;
    const int tid = threadIdx.x;
    const float* xr = x     + row * (long)E_;
    const float* ar = g_att + row * (long)E_;

    float v[3]; float s = 0.f;
#pragma unroll
    for (int k = 0; k < 3; k++) { int j = tid + 256 * k; v[k] = xr[j] + ar[j]; s += v[k]; }
    float mean = blk_sum(s, sh) * (1.0f / 768.0f);

    float q = 0.f;
#pragma unroll
    for (int k = 0; k < 3; k++) { float d = v[k] - mean; q += d * d; }
    float rstd = rsqrtf(blk_sum(q, sh) * (1.0f / 768.0f) + 1e-5f);

#pragma unroll
    for (int k = 0; k < 3; k++) {
        int j = tid + 256 * k;
        float y = (v[k] - mean) * rstd * g[j] + be[j];
        g_x1[row * (long)E_ + j] = y;
        if (j < NQ_) g_qf[row * (long)NQ_ + j] = round_tf(cosf(y + th_ry[j]));
    }
}

// ---------------- LN2 -> out ----------------
__global__ __launch_bounds__(256)
void ln2_kernel(const float* __restrict__ g, const float* __restrict__ be,
                float* __restrict__ out)
{
    __shared__ float sh[8];
    const long row = blockIdx.x;
    const int tid = threadIdx.x;
    const float* xr = g_x1  + row * (long)E_;
    const float* fr = g_ffn + row * (long)E_;

    float v[3]; float s = 0.f;
#pragma unroll
    for (int k = 0; k < 3; k++) { int j = tid + 256 * k; v[k] = xr[j] + fr[j]; s += v[k]; }
    float mean = blk_sum(s, sh) * (1.0f / 768.0f);

    float q = 0.f;
#pragma unroll
    for (int k = 0; k < 3; k++) { float d = v[k] - mean; q += d * d; }
    float rstd = rsqrtf(blk_sum(q, sh) * (1.0f / 768.0f) + 1e-5f);

#pragma unroll
    for (int k = 0; k < 3; k++) {
        int j = tid + 256 * k;
        out[row * (long)E_ + j] = (v[k] - mean) * rstd * g[j] + be[j];
    }
}

// ---------------- launch ----------------
extern "C" void kernel_launch(void* const* d_in, const int* in_sizes, int n_in,
                              void* d_out, int out_size)
{
    (void)in_sizes; (void)n_in; (void)out_size;
    const float* x     = (const float*)d_in[0];
    const float* Wp    = (const float*)d_in[1];
    const float* th_rx = (const float*)d_in[2];
    const float* th_ry = (const float*)d_in[3];
    const float* W1    = (const float*)d_in[4];
    const float* b1    = (const float*)d_in[5];
    const float* W2    = (const float*)d_in[6];
    const float* b2    = (const float*)d_in[7];
    const float* g1    = (const float*)d_in[8];
    const float* be1   = (const float*)d_in[9];
    const float* g2    = (const float*)d_in[10];
    const float* be2   = (const float*)d_in[11];
    float* out = (float*)d_out;

    void *p;
    cudaGetSymbolAddress(&p, g_xr);  float* xr  = (float*)p;
    cudaGetSymbolAddress(&p, g_wpr); float* wpr = (float*)p;
    cudaGetSymbolAddress(&p, g_w1r); float* w1r = (float*)p;
    cudaGetSymbolAddress(&p, g_w2r); float* w2r = (float*)p;
    cudaGetSymbolAddress(&p, g_qa);  float* qa  = (float*)p;
    cudaGetSymbolAddress(&p, g_qaT); float* qaT = (float*)p;
    cudaGetSymbolAddress(&p, g_sc);  float* sc  = (float*)p;
    cudaGetSymbolAddress(&p, g_att); float* att = (float*)p;
    cudaGetSymbolAddress(&p, g_qf);  float* qf  = (float*)p;
    cudaGetSymbolAddress(&p, g_h);   float* h   = (float*)p;
    cudaGetSymbolAddress(&p, g_ffn); float* ffn = (float*)p;

    // 0) pre-round GEMM inputs to tf32
    round_kernel<<<(NTOK * (E_ / 4) + 255) / 256, 256>>>(x,  xr,  (long)NTOK * E_ / 4);
    round_kernel<<<(E_ * E_ / 4 + 255) / 256, 256>>>(Wp, wpr, (long)E_ * E_ / 4);
    round_kernel<<<(FF_ * NQ_ / 4 + 255) / 256, 256>>>(W1, w1r, (long)FF_ * NQ_ / 4);
    round_kernel<<<(E_ * FF_ / 4 + 255) / 256, 256>>>(W2, w2r, (long)E_ * FF_ / 4);

    dim3 blk(256);

    // 1) proj + cos -> qa (rounded; also writes qaT)
    gemm_tf32<EPI_QA><<<dim3(E_ / 128, NTOK / 128, 1), blk>>>(
        xr, wpr, qa, E_, E_, E_, E_, 0, 0, 0, th_rx);

    // 2) scores = qa qa^T / sqrt(8), batched over 8
    gemm_tf32<EPI_SCORES><<<dim3(S_ / 128, S_ / 128, B_), blk>>>(
        qa, qa, sc, E_, E_, E_, S_,
        (long)S_ * E_, (long)S_ * E_, (long)S_ * S_, nullptr);

    // 3) softmax rows (-> rounded probs)
    softmax_kernel<<<NTOK, 256>>>();

    // 4) attn_out = P @ qa  (B = qaT [e][s], K-contiguous)
    gemm_tf32<EPI_NONE><<<dim3(E_ / 128, S_ / 128, B_), blk>>>(
        sc, qaT, att, S_, S_, S_, E_,
        (long)S_ * S_, (long)E_ * S_, (long)S_ * E_, nullptr);

    // 5) x1 = LN(x + att); qf = cos(x1[:, :NQ] + theta_ry) (rounded)
    ln1_qf_kernel<<<NTOK, 256>>>(x, g1, be1, th_ry);

    // 6) h = relu(qf @ W1^T + b1) (rounded)
    gemm_tf32<EPI_RELU><<<dim3(FF_ / 128, NTOK / 128, 1), blk>>>(
        qf, w1r, h, NQ_, NQ_, NQ_, FF_, 0, 0, 0, b1);

    // 7) ffn = h @ W2^T + b2
    gemm_tf32<EPI_BIAS><<<dim3(E_ / 128, NTOK / 128, 1), blk>>>(
        h, w2r, ffn, FF_, FF_, FF_, E_, 0, 0, 0, b2);

    // 8) out = LN(x1 + ffn)
    ln2_kernel<<<NTOK, 256>>>(g2, be2, out);
}

// round 11
// speedup vs baseline: 1.8943x; 1.8734x over previous
#include <cuda_runtime.h>
#include <cuda_fp16.h>
#include <cstdint>

#define B_    8
#define S_    2048
#define E_    768
#define FF_   3072
#define NQ_   128
#define NTOK  (B_ * S_)

// ---------------- static scratch (device globals; allocation-free) ----------------
__device__ __half g_xh [NTOK * E_];                //  25 MB  fp16 x
__device__ __half g_wph[E_ * E_];                  // 1.2 MB  fp16 Wp
__device__ __half g_w1h[FF_ * NQ_];                // 0.8 MB  fp16 W1
__device__ __half g_w2h[E_ * FF_];                 // 4.7 MB  fp16 W2
__device__ __half g_qah[NTOK * E_];                //  25 MB  cos(proj+theta_rx)
__device__ __half g_qaTh[B_ * E_ * S_];            //  25 MB  [b][e][s]
__device__ float  g_sc [(long)B_ * S_ * S_];       // 134 MB  raw scores (f32)
__device__ __half g_ph [(long)B_ * S_ * S_];       //  67 MB  probs (fp16)
__device__ float  g_att[NTOK * E_];                //  50 MB
__device__ float  g_x1 [NTOK * E_];                //  50 MB
__device__ __half g_qfh[NTOK * NQ_];               //   4 MB
__device__ __half g_hh [NTOK * FF_];               //  96 MB  relu hidden
__device__ float  g_ffn[NTOK * E_];                //  50 MB

// ---------------- helpers ----------------
__device__ __forceinline__ void mma_f16(float c[4], const uint32_t a[4], const uint32_t b[2]) {
    asm volatile(
        "mma.sync.aligned.m16n8k16.row.col.f32.f16.f16.f32 "
        "{%0,%1,%2,%3}, {%4,%5,%6,%7}, {%8,%9}, {%0,%1,%2,%3};\n"
        : "+f"(c[0]), "+f"(c[1]), "+f"(c[2]), "+f"(c[3])
        : "r"(a[0]), "r"(a[1]), "r"(a[2]), "r"(a[3]), "r"(b[0]), "r"(b[1]));
}

__device__ __forceinline__ void cp16(void* dst, const void* src) {
    unsigned d = (unsigned)__cvta_generic_to_shared(dst);
    asm volatile("cp.async.cg.shared.global [%0], [%1], 16;" :: "r"(d), "l"(src));
}

// ---------------- fp16 GEMM, TN: C[M,N] = A[M,K] @ B[N,K]^T ----------------
// BM=BN=128, BK=32 halves. 256 threads = 8 warps (2m x 4n), warp tile 64x32.
// 3-stage cp.async ring, one __syncthreads per iter.
enum { EPI_QA = 0, EPI_SCORES = 1, EPI_NONE = 2, EPI_RELU = 3, EPI_BIAS = 4 };

#define ROW_U32   20
#define SLOT_U32  (128 * ROW_U32)        // one tile: 2560 u32 = 10240 B
#define STAGE_U32 (2 * SLOT_U32)         // A + B
#define DSM_BYTES (3 * STAGE_U32 * 4)    // 61440 B

template <int EPI>
__global__ __launch_bounds__(256, 2)
void gemm_f16(const __half* __restrict__ Aall, const __half* __restrict__ Ball,
              float* __restrict__ Cfall, __half* __restrict__ Chall,
              int K, int lda, int ldb, int ldc,
              long bsA, long bsB, long bsC,
              const float* __restrict__ vec)
{
    extern __shared__ __align__(16) uint32_t dsm[];

    const __half* A  = Aall + (long)blockIdx.z * bsA;
    const __half* Bp = Ball + (long)blockIdx.z * bsB;
    float*  Cf = Cfall ? Cfall + (long)blockIdx.z * bsC : nullptr;   // BUGFIX R10:
    __half* Ch = Chall ? Chall + (long)blockIdx.z * bsC : nullptr;   // batch offset C

    const int tid  = threadIdx.x;
    const int wid  = tid >> 5, lane = tid & 31;
    const int wm   = wid & 1,  wn   = wid >> 1;      // 2 x 4 warps
    const int g    = lane >> 2, cc  = lane & 3;

    const int row0 = blockIdx.y * 128;
    const int col0 = blockIdx.x * 128;

    float acc[4][4][4];
#pragma unroll
    for (int i = 0; i < 4; i++)
#pragma unroll
        for (int j = 0; j < 4; j++)
#pragma unroll
            for (int t = 0; t < 4; t++) acc[i][j][t] = 0.f;

    const int nk = K / 32;

    auto load_stage = [&](int slot, int kt) {
        const int kb = kt * 32;                       // halves
        uint32_t* sAb = dsm + slot * STAGE_U32;
        uint32_t* sBb = sAb + SLOT_U32;
#pragma unroll
        for (int u = 0; u < 2; u++) {                 // 512 chunks / 256 thr
            int c  = tid + u * 256;
            int rw = c >> 2, q = c & 3;
            cp16(&sAb[rw * ROW_U32 + q * 4], A  + (long)(row0 + rw) * lda + kb + q * 8);
            cp16(&sBb[rw * ROW_U32 + q * 4], Bp + (long)(col0 + rw) * ldb + kb + q * 8);
        }
        asm volatile("cp.async.commit_group;");
    };

    load_stage(0, 0);
    load_stage(1, 1);

    for (int kt = 0; kt < nk; kt++) {
        asm volatile("cp.async.wait_group 1;");
        __syncthreads();
        if (kt + 2 < nk) load_stage((kt + 2) % 3, kt + 2);
        else             asm volatile("cp.async.commit_group;");

        const uint32_t* sAb = dsm + (kt % 3) * STAGE_U32;
        const uint32_t* sBb = sAb + SLOT_U32;

#pragma unroll
        for (int s = 0; s < 2; s++) {                 // two k16 slices
            const int kw = s * 8;                     // u32 words
            uint32_t a[4][4], b[4][2];
#pragma unroll
            for (int i = 0; i < 4; i++) {
                const int m = wm * 64 + i * 16;
                a[i][0] = sAb[(m + g    ) * ROW_U32 + kw + cc    ];
                a[i][1] = sAb[(m + g + 8) * ROW_U32 + kw + cc    ];
                a[i][2] = sAb[(m + g    ) * ROW_U32 + kw + cc + 4];
                a[i][3] = sAb[(m + g + 8) * ROW_U32 + kw + cc + 4];
            }
#pragma unroll
            for (int j = 0; j < 4; j++) {
                const int n = wn * 32 + j * 8 + g;
                b[j][0] = sBb[n * ROW_U32 + kw + cc    ];
                b[j][1] = sBb[n * ROW_U32 + kw + cc + 4];
            }
#pragma unroll
            for (int i = 0; i < 4; i++)
#pragma unroll
                for (int j = 0; j < 4; j++)
                    mma_f16(acc[i][j], a[i], b[j]);
        }
    }

    // ---------------- epilogue ----------------
    const float scale = 0.35355339059327376f;  // 1/sqrt(8)
#pragma unroll
    for (int i = 0; i < 4; i++) {
        int gm = row0 + wm * 64 + i * 16 + g;
#pragma unroll
        for (int j = 0; j < 4; j++) {
            int gn = col0 + wn * 32 + j * 8 + 2 * cc;
#pragma unroll
            for (int hh = 0; hh < 2; hh++) {
                int gmr = gm + hh * 8;
                float e0 = acc[i][j][hh * 2 + 0];
                float e1 = acc[i][j][hh * 2 + 1];
                if (EPI == EPI_QA) {
                    __half q0 = __float2half_rn(cosf(e0 + vec[gn]));
                    __half q1 = __float2half_rn(cosf(e1 + vec[gn + 1]));
                    *reinterpret_cast<__half2*>(&Ch[(long)gmr * ldc + gn]) =
                        __halves2half2(q0, q1);
                    int bb = gmr >> 11, ss = gmr & (S_ - 1);
                    g_qaTh[((long)bb * E_ + gn    ) * S_ + ss] = q0;
                    g_qaTh[((long)bb * E_ + gn + 1) * S_ + ss] = q1;
                } else if (EPI == EPI_RELU) {
                    __half q0 = __float2half_rn(fmaxf(e0 + vec[gn], 0.f));
                    __half q1 = __float2half_rn(fmaxf(e1 + vec[gn + 1], 0.f));
                    *reinterpret_cast<__half2*>(&Ch[(long)gmr * ldc + gn]) =
                        __halves2half2(q0, q1);
                } else {
                    if (EPI == EPI_SCORES) { e0 *= scale; e1 *= scale; }
                    else if (EPI == EPI_BIAS) { e0 += vec[gn]; e1 += vec[gn + 1]; }
                    *reinterpret_cast<float2*>(&Cf[(long)gmr * ldc + gn]) =
                        make_float2(e0, e1);
                }
            }
        }
    }
}

// ---------------- f32 -> fp16 conversion ----------------
__global__ __launch_bounds__(256)
void cvt_kernel(const float* __restrict__ in, __half* __restrict__ out, long n4)
{
    long i = (long)blockIdx.x * 256 + threadIdx.x;
    if (i < n4) {
        float4 v = reinterpret_cast<const float4*>(in)[i];
        reinterpret_cast<__half2*>(out)[2 * i]     = __floats2half2_rn(v.x, v.y);
        reinterpret_cast<__half2*>(out)[2 * i + 1] = __floats2half2_rn(v.z, v.w);
    }
}

// ---------------- block reductions ----------------
__device__ __forceinline__ float blk_sum(float v, float* sh) {
#pragma unroll
    for (int o = 16; o > 0; o >>= 1) v += __shfl_xor_sync(0xffffffffu, v, o);
    int w = threadIdx.x >> 5;
    if ((threadIdx.x & 31) == 0) sh[w] = v;
    __syncthreads();
    float t = 0.f;
#pragma unroll
    for (int i = 0; i < 8; i++) t += sh[i];
    __syncthreads();
    return t;
}
__device__ __forceinline__ float blk_max(float v, float* sh) {
#pragma unroll
    for (int o = 16; o > 0; o >>= 1) v = fmaxf(v, __shfl_xor_sync(0xffffffffu, v, o));
    int w = threadIdx.x >> 5;
    if ((threadIdx.x & 31) == 0) sh[w] = v;
    __syncthreads();
    float t = sh[0];
#pragma unroll
    for (int i = 1; i < 8; i++) t = fmaxf(t, sh[i]);
    __syncthreads();
    return t;
}

// ---------------- softmax rows: f32 scores -> fp16 probs ----------------
__global__ __launch_bounds__(256)
void softmax_kernel()
{
    __shared__ float sh[8];
    const long row = blockIdx.x;
    const float* sr = g_sc + row * (long)S_;
    __half* pr = g_ph + row * (long)S_;
    const int tid = threadIdx.x;

    float v[8];
    float m = -1e30f;
#pragma unroll
    for (int k = 0; k < 8; k++) { v[k] = sr[tid + k * 256]; m = fmaxf(m, v[k]); }
    m = blk_max(m, sh);

    float s = 0.f;
#pragma unroll
    for (int k = 0; k < 8; k++) { v[k] = __expf(v[k] - m); s += v[k]; }
    s = blk_sum(s, sh);

    const float inv = 1.f / s;
#pragma unroll
    for (int k = 0; k < 8; k++) pr[tid + k * 256] = __float2half_rn(v[k] * inv);
}

// ---------------- LN1 -> x1 (f32), qf (fp16) ----------------
__global__ __launch_bounds__(256)
void ln1_qf_kernel(const float* __restrict__ x, const float* __restrict__ g,
                   const float* __restrict__ be, const float* __restrict__ th_ry)
{
    __shared__ float sh[8];
    const long row = blockIdx.x;
    const int tid = threadIdx.x;
    const float* xr = x     + row * (long)E_;
    const float* ar = g_att + row * (long)E_;

    float v[3]; float s = 0.f;
#pragma unroll
    for (int k = 0; k < 3; k++) { int j = tid + 256 * k; v[k] = xr[j] + ar[j]; s += v[k]; }
    float mean = blk_sum(s, sh) * (1.0f / 768.0f);

    float q = 0.f;
#pragma unroll
    for (int k = 0; k < 3; k++) { float d = v[k] - mean; q += d * d; }
    float rstd = rsqrtf(blk_sum(q, sh) * (1.0f / 768.0f) + 1e-5f);

#pragma unroll
    for (int k = 0; k < 3; k++) {
        int j = tid + 256 * k;
        float y = (v[k] - mean) * rstd * g[j] + be[j];
        g_x1[row * (long)E_ + j] = y;
        if (j < NQ_) g_qfh[row * (long)NQ_ + j] = __float2half_rn(cosf(y + th_ry[j]));
    }
}

// ---------------- LN2 -> out ----------------
__global__ __launch_bounds__(256)
void ln2_kernel(const float* __restrict__ g, const float* __restrict__ be,
                float* __restrict__ out)
{
    __shared__ float sh[8];
    const long row = blockIdx.x;
    const int tid = threadIdx.x;
    const float* xr = g_x1  + row * (long)E_;
    const float* fr = g_ffn + row * (long)E_;

    float v[3]; float s = 0.f;
#pragma unroll
    for (int k = 0; k < 3; k++) { int j = tid + 256 * k; v[k] = xr[j] + fr[j]; s += v[k]; }
    float mean = blk_sum(s, sh) * (1.0f / 768.0f);

    float q = 0.f;
#pragma unroll
    for (int k = 0; k < 3; k++) { float d = v[k] - mean; q += d * d; }
    float rstd = rsqrtf(blk_sum(q, sh) * (1.0f / 768.0f) + 1e-5f);

#pragma unroll
    for (int k = 0; k < 3; k++) {
        int j = tid + 256 * k;
        out[row * (long)E_ + j] = (v[k] - mean) * rstd * g[j] + be[j];
    }
}

// ---------------- launch ----------------
extern "C" void kernel_launch(void* const* d_in, const int* in_sizes, int n_in,
                              void* d_out, int out_size)
{
    (void)in_sizes; (void)n_in; (void)out_size;
    const float* x     = (const float*)d_in[0];
    const float* Wp    = (const float*)d_in[1];
    const float* th_rx = (const float*)d_in[2];
    const float* th_ry = (const float*)d_in[3];
    const float* W1    = (const float*)d_in[4];
    const float* b1    = (const float*)d_in[5];
    const float* W2    = (const float*)d_in[6];
    const float* b2    = (const float*)d_in[7];
    const float* g1    = (const float*)d_in[8];
    const float* be1   = (const float*)d_in[9];
    const float* g2    = (const float*)d_in[10];
    const float* be2   = (const float*)d_in[11];
    float* out = (float*)d_out;

    void *p;
    cudaGetSymbolAddress(&p, g_xh);   __half* xh   = (__half*)p;
    cudaGetSymbolAddress(&p, g_wph);  __half* wph  = (__half*)p;
    cudaGetSymbolAddress(&p, g_w1h);  __half* w1h  = (__half*)p;
    cudaGetSymbolAddress(&p, g_w2h);  __half* w2h  = (__half*)p;
    cudaGetSymbolAddress(&p, g_qah);  __half* qah  = (__half*)p;
    cudaGetSymbolAddress(&p, g_qaTh); __half* qaTh = (__half*)p;
    cudaGetSymbolAddress(&p, g_sc);   float*  sc   = (float*)p;
    cudaGetSymbolAddress(&p, g_ph);   __half* ph   = (__half*)p;
    cudaGetSymbolAddress(&p, g_att);  float*  att  = (float*)p;
    cudaGetSymbolAddress(&p, g_qfh);  __half* qfh  = (__half*)p;
    cudaGetSymbolAddress(&p, g_hh);   __half* hh   = (__half*)p;
    cudaGetSymbolAddress(&p, g_ffn);  float*  ffn  = (float*)p;

    cudaFuncSetAttribute(gemm_f16<EPI_QA>,     cudaFuncAttributeMaxDynamicSharedMemorySize, DSM_BYTES);
    cudaFuncSetAttribute(gemm_f16<EPI_SCORES>, cudaFuncAttributeMaxDynamicSharedMemorySize, DSM_BYTES);
    cudaFuncSetAttribute(gemm_f16<EPI_NONE>,   cudaFuncAttributeMaxDynamicSharedMemorySize, DSM_BYTES);
    cudaFuncSetAttribute(gemm_f16<EPI_RELU>,   cudaFuncAttributeMaxDynamicSharedMemorySize, DSM_BYTES);
    cudaFuncSetAttribute(gemm_f16<EPI_BIAS>,   cudaFuncAttributeMaxDynamicSharedMemorySize, DSM_BYTES);

    // 0) convert GEMM inputs to fp16
    cvt_kernel<<<(NTOK * (E_ / 4) + 255) / 256, 256>>>(x,  xh,  (long)NTOK * E_ / 4);
    cvt_kernel<<<(E_ * E_ / 4 + 255) / 256, 256>>>(Wp, wph, (long)E_ * E_ / 4);
    cvt_kernel<<<(FF_ * NQ_ / 4 + 255) / 256, 256>>>(W1, w1h, (long)FF_ * NQ_ / 4);
    cvt_kernel<<<(E_ * FF_ / 4 + 255) / 256, 256>>>(W2, w2h, (long)E_ * FF_ / 4);

    dim3 blk(256);

    // 1) proj + cos -> qa (fp16; also writes qaT)
    gemm_f16<EPI_QA><<<dim3(E_ / 128, NTOK / 128, 1), blk, DSM_BYTES>>>(
        xh, wph, nullptr, qah, E_, E_, E_, E_, 0, 0, 0, th_rx);

    // 2) scores = qa qa^T / sqrt(8) (f32)
    gemm_f16<EPI_SCORES><<<dim3(S_ / 128, S_ / 128, B_), blk, DSM_BYTES>>>(
        qah, qah, sc, nullptr, E_, E_, E_, S_,
        (long)S_ * E_, (long)S_ * E_, (long)S_ * S_, nullptr);

    // 3) softmax rows -> fp16 probs
    softmax_kernel<<<NTOK, 256>>>();

    // 4) attn_out = P @ qa  (B = qaT, K-contiguous) -> f32
    gemm_f16<EPI_NONE><<<dim3(E_ / 128, S_ / 128, B_), blk, DSM_BYTES>>>(
        ph, qaTh, att, nullptr, S_, S_, S_, E_,
        (long)S_ * S_, (long)E_ * S_, (long)S_ * E_, nullptr);

    // 5) x1 = LN(x + att); qf = cos(x1[:, :NQ] + theta_ry) (fp16)
    ln1_qf_kernel<<<NTOK, 256>>>(x, g1, be1, th_ry);

    // 6) h = relu(qf @ W1^T + b1) (fp16)
    gemm_f16<EPI_RELU><<<dim3(FF_ / 128, NTOK / 128, 1), blk, DSM_BYTES>>>(
        qfh, w1h, nullptr, hh, NQ_, NQ_, NQ_, FF_, 0, 0, 0, b1);

    // 7) ffn = h @ W2^T + b2 (f32)
    gemm_f16<EPI_BIAS><<<dim3(E_ / 128, NTOK / 128, 1), blk, DSM_BYTES>>>(
        hh, w2h, ffn, nullptr, FF_, FF_, FF_, E_, 0, 0, 0, b2);

    // 8) out = LN(x1 + ffn)
    ln2_kernel<<<NTOK, 256>>>(g2, be2, out);
}